// round 5
// baseline (speedup 1.0000x reference)
#include <cuda_runtime.h>
#include <cuda_fp16.h>
#include <cstdint>

#define IN_DIM   32768
#define CLASSES  100
#define BATCH    4096
#define NPAD     112
#define SPLITS   4
#define KSPLIT   (IN_DIM / SPLITS)       // 8192
#define KSTAGE   64
#define NITER    (KSPLIT / KSTAGE)       // 128
#define ABYTES   (128 * 128)             // 16384 (128 rows x 64 halves)
#define BBYTES   (NPAD * 128)            // 14336
#define STAGE_BYTES (ABYTES + BBYTES)    // 30720
#define THREADS  256

#define SWZ(o) ((o) ^ (((o) >> 3) & 0x70))

__device__ __half g_signW[(size_t)NPAD * IN_DIM];            // 7.3 MB fp16 sign(W), padded
__device__ float  g_partial[(size_t)SPLITS * BATCH * NPAD];  // 7.3 MB split-K partials

// ---------------------------------------------------------------- helpers
__device__ __forceinline__ uint32_t smem_u32(const void* p) {
    uint32_t a;
    asm("{ .reg .u64 t; cvta.to.shared.u64 t, %1; cvt.u32.u64 %0, t; }" : "=r"(a) : "l"(p));
    return a;
}
__device__ __forceinline__ void ldsm_x4(uint32_t& r0, uint32_t& r1, uint32_t& r2, uint32_t& r3,
                                        uint32_t addr) {
    asm volatile("ldmatrix.sync.aligned.m8n8.x4.shared.b16 {%0,%1,%2,%3}, [%4];"
                 : "=r"(r0), "=r"(r1), "=r"(r2), "=r"(r3) : "r"(addr));
}
__device__ __forceinline__ void mma16816(float* c, uint32_t a0, uint32_t a1, uint32_t a2,
                                         uint32_t a3, uint32_t b0, uint32_t b1) {
    asm volatile(
        "mma.sync.aligned.m16n8k16.row.col.f32.f16.f16.f32 "
        "{%0,%1,%2,%3}, {%4,%5,%6,%7}, {%8,%9}, {%0,%1,%2,%3};"
        : "+f"(c[0]), "+f"(c[1]), "+f"(c[2]), "+f"(c[3])
        : "r"(a0), "r"(a1), "r"(a2), "r"(a3), "r"(b0), "r"(b1));
}
__device__ __forceinline__ void sts128(uint32_t addr, uint32_t u0, uint32_t u1,
                                       uint32_t u2, uint32_t u3) {
    asm volatile("st.shared.v4.b32 [%0], {%1,%2,%3,%4};"
                 :: "r"(addr), "r"(u0), "r"(u1), "r"(u2), "r"(u3) : "memory");
}
__device__ __forceinline__ void cpasync16(uint32_t saddr, const void* gptr) {
    asm volatile("cp.async.cg.shared.global [%0], [%1], 16;"
                 :: "r"(saddr), "l"(gptr) : "memory");
}
__device__ __forceinline__ uint32_t packh2(float lo, float hi) {
    __half2 h = __floats2half2_rn(lo, hi);
    return *reinterpret_cast<uint32_t*>(&h);
}

// ---------------------------------------------------------------- kernel 1: sign(W) -> fp16
__global__ void sign_kernel(const float* __restrict__ W) {
    int i = blockIdx.x * 256 + threadIdx.x;     // NPAD * IN_DIM
    int n = i >> 15;
    int k = i & (IN_DIM - 1);
    float v = 0.f;
    if (n < CLASSES) {
        float w = W[n * IN_DIM + k];
        v = (w > 0.f) ? 1.f : ((w < 0.f) ? -1.f : 0.f);
    }
    g_signW[i] = __float2half_rn(v);
}

// ---------------------------------------------------------------- kernel 2: split-K fp16 GEMM
__global__ __launch_bounds__(THREADS, 1)
void binmm_kernel(const float* __restrict__ x) {
    extern __shared__ char smraw[];
    uint32_t sb = (smem_u32(smraw) + 1023u) & ~1023u;

    const int tid  = threadIdx.x;
    const int lane = tid & 31;
    const int w    = tid >> 5;
    const int bid  = blockIdx.x;
    const int mtile = bid & 31;
    const int split = bid >> 5;
    const size_t m0 = (size_t)mtile * 128;
    const int kbase = split * KSPLIT;

    // ---- producer geometry (per thread) ----
    const float* pA[4];
    uint32_t sA[4];
    const __half* pB[4];
    uint32_t sB[4];
    bool bAct[4];
    #pragma unroll
    for (int j = 0; j < 4; j++) {
        int g = tid + THREADS * j;               // A: 1024 granules of 16B smem (8 halves)
        int row = g >> 3, c16 = g & 7;
        pA[j] = x + (m0 + (size_t)row) * IN_DIM + kbase + c16 * 8;
        sA[j] = SWZ((uint32_t)(row * 128 + c16 * 16));
        bAct[j] = g < (NPAD * 8);                // B: 896 granules
        int rb = g >> 3, cb = g & 7;
        pB[j] = g_signW + (size_t)rb * IN_DIM + kbase + cb * 8;
        sB[j] = SWZ((uint32_t)(rb * 128 + cb * 16));
    }

    // ---- ldmatrix base addresses ----
    const int lm = lane >> 3, lr = lane & 7;
    const int arow = 16 * w + ((lm & 1) ? 8 : 0) + lr;
    const uint32_t aOff = SWZ((uint32_t)(arow * 128 + (lm >> 1) * 16));
    const int brow = ((lm & 1) ? 8 : 0) + lr;
    const uint32_t bOff = SWZ((uint32_t)(brow * 128 + (lm >> 1) * 16));

    float acc[14][4];
    #pragma unroll
    for (int t = 0; t < 14; t++)
        #pragma unroll
        for (int q = 0; q < 4; q++) acc[t][q] = 0.f;

    float4 fa[8];

    #define LOADA(it) do {                                                        \
        _Pragma("unroll")                                                         \
        for (int j = 0; j < 4; j++) {                                             \
            const float* _p = pA[j] + (size_t)(it) * KSTAGE;                      \
            fa[j * 2]     = *reinterpret_cast<const float4*>(_p);                 \
            fa[j * 2 + 1] = *reinterpret_cast<const float4*>(_p + 4);             \
        }                                                                         \
    } while (0)

    #define STSA(soff) do {                                                       \
        _Pragma("unroll")                                                         \
        for (int j = 0; j < 4; j++) {                                             \
            float4 f0 = fa[j * 2], f1 = fa[j * 2 + 1];                            \
            sts128(sb + (soff) + sA[j],                                           \
                   packh2(f0.x, f0.y), packh2(f0.z, f0.w),                        \
                   packh2(f1.x, f1.y), packh2(f1.z, f1.w));                       \
        }                                                                         \
    } while (0)

    #define CPB(it, soff) do {                                                    \
        _Pragma("unroll")                                                         \
        for (int j = 0; j < 4; j++)                                               \
            if (bAct[j])                                                          \
                cpasync16(sb + (soff) + ABYTES + sB[j], pB[j] + (size_t)(it) * KSTAGE); \
    } while (0)

    // ---- prologue: stages 0 and 1 ----
    LOADA(0); STSA(0); CPB(0, 0);
    asm volatile("cp.async.commit_group;" ::: "memory");
    LOADA(1); STSA(STAGE_BYTES); CPB(1, STAGE_BYTES);
    asm volatile("cp.async.commit_group;" ::: "memory");

    // ---- mainloop ----
    int s = 0;
    for (int i = 0; i < NITER; i++) {
        asm volatile("cp.async.wait_group 1;" ::: "memory");
        __syncthreads();

        const bool pf = (i + 2) < NITER;
        int s2 = s + 2; if (s2 >= 3) s2 -= 3;
        const uint32_t soff  = (uint32_t)s * STAGE_BYTES;
        const uint32_t soff2 = (uint32_t)s2 * STAGE_BYTES;

        if (pf) {
            LOADA(i + 2);
            CPB(i + 2, soff2);
        }
        asm volatile("cp.async.commit_group;" ::: "memory");

        // compute stage s: 4 k16 steps
        // NOTE: k-step advance on a swizzled address is XOR (bits 5-6 of the
        // pre-swizzle column are 0), NOT add — add carries into the row bits.
        const uint32_t aA = sb + soff + aOff;
        const uint32_t bA = sb + soff + ABYTES + bOff;
        #pragma unroll
        for (int t = 0; t < 4; t++) {
            uint32_t a0, a1, a2, a3;
            ldsm_x4(a0, a1, a2, a3, aA ^ (32u * t));
            #pragma unroll
            for (int p = 0; p < 7; p++) {
                uint32_t b0, b1, b2, b3;
                ldsm_x4(b0, b1, b2, b3, (bA + p * 2048) ^ (32u * t));
                mma16816(acc[2 * p],     a0, a1, a2, a3, b0, b2);
                mma16816(acc[2 * p + 1], a0, a1, a2, a3, b1, b3);
            }
        }

        if (pf) STSA(soff2);
        if (++s == 3) s = 0;
    }

    // ---- epilogue: store split-K partials ----
    const int r0 = 16 * w + (lane >> 2);
    #pragma unroll
    for (int nt = 0; nt < 14; nt++) {
        int n = nt * 8 + (lane & 3) * 2;
        size_t idx = ((size_t)split * BATCH + m0 + r0) * NPAD + n;
        *reinterpret_cast<float2*>(&g_partial[idx]) = make_float2(acc[nt][0], acc[nt][1]);
        *reinterpret_cast<float2*>(&g_partial[idx + 8 * NPAD]) = make_float2(acc[nt][2], acc[nt][3]);
    }
    #undef LOADA
    #undef STSA
    #undef CPB
}

// ---------------------------------------------------------------- kernel 3: split-K reduce
__global__ void reduce_kernel(float* __restrict__ out) {
    int idx = blockIdx.x * 256 + threadIdx.x;   // BATCH * CLASSES
    int m = idx / CLASSES;
    int n = idx - m * CLASSES;
    const float scale = 0.0055242717280199026f; // 1/sqrt(32768)
    float a = 0.f;
    #pragma unroll
    for (int s = 0; s < SPLITS; s++)
        a += g_partial[((size_t)s * BATCH + m) * NPAD + n];
    out[idx] = a * scale;
}

// ---------------------------------------------------------------- launch
extern "C" void kernel_launch(void* const* d_in, const int* in_sizes, int n_in,
                              void* d_out, int out_size) {
    const float* x = (const float*)d_in[0];
    const float* W = (const float*)d_in[1];
    float* out = (float*)d_out;

    const int SMEM_DYN = 3 * STAGE_BYTES + 1024;
    cudaFuncSetAttribute(binmm_kernel, cudaFuncAttributeMaxDynamicSharedMemorySize, SMEM_DYN);

    sign_kernel<<<(NPAD * IN_DIM) / 256, 256>>>(W);
    binmm_kernel<<<SPLITS * 32, THREADS, SMEM_DYN>>>(x);
    reduce_kernel<<<(BATCH * CLASSES) / 256, 256>>>(out);
}

// round 6
// speedup vs baseline: 1.1201x; 1.1201x over previous
#include <cuda_runtime.h>
#include <cuda_fp16.h>
#include <cstdint>

#define IN_DIM   32768
#define CLASSES  100
#define BATCH    4096
#define NPAD     112
#define SPLITS   8
#define KSPLIT   (IN_DIM / SPLITS)       // 4096
#define KSTAGE   64
#define NITER    (KSPLIT / KSTAGE)       // 64
#define ABYTES   (128 * 128)             // 16384 (128 rows x 64 halves)
#define BBYTES   (NPAD * 128)            // 14336
#define STAGE_BYTES (ABYTES + BBYTES)    // 30720
#define THREADS  256

#define SWZ(o) ((o) ^ (((o) >> 3) & 0x70))

__device__ __half g_signW[(size_t)NPAD * IN_DIM];            // 7.3 MB fp16 sign(W), padded
__device__ float  g_partial[(size_t)SPLITS * BATCH * NPAD];  // 14.7 MB split-K partials

// ---------------------------------------------------------------- helpers
__device__ __forceinline__ uint32_t smem_u32(const void* p) {
    uint32_t a;
    asm("{ .reg .u64 t; cvta.to.shared.u64 t, %1; cvt.u32.u64 %0, t; }" : "=r"(a) : "l"(p));
    return a;
}
__device__ __forceinline__ void ldsm_x4(uint32_t& r0, uint32_t& r1, uint32_t& r2, uint32_t& r3,
                                        uint32_t addr) {
    asm volatile("ldmatrix.sync.aligned.m8n8.x4.shared.b16 {%0,%1,%2,%3}, [%4];"
                 : "=r"(r0), "=r"(r1), "=r"(r2), "=r"(r3) : "r"(addr));
}
__device__ __forceinline__ void mma16816(float* c, uint32_t a0, uint32_t a1, uint32_t a2,
                                         uint32_t a3, uint32_t b0, uint32_t b1) {
    asm volatile(
        "mma.sync.aligned.m16n8k16.row.col.f32.f16.f16.f32 "
        "{%0,%1,%2,%3}, {%4,%5,%6,%7}, {%8,%9}, {%0,%1,%2,%3};"
        : "+f"(c[0]), "+f"(c[1]), "+f"(c[2]), "+f"(c[3])
        : "r"(a0), "r"(a1), "r"(a2), "r"(a3), "r"(b0), "r"(b1));
}
__device__ __forceinline__ void sts128(uint32_t addr, uint32_t u0, uint32_t u1,
                                       uint32_t u2, uint32_t u3) {
    asm volatile("st.shared.v4.b32 [%0], {%1,%2,%3,%4};"
                 :: "r"(addr), "r"(u0), "r"(u1), "r"(u2), "r"(u3) : "memory");
}
__device__ __forceinline__ void cpasync16(uint32_t saddr, const void* gptr) {
    asm volatile("cp.async.cg.shared.global [%0], [%1], 16;"
                 :: "r"(saddr), "l"(gptr) : "memory");
}
__device__ __forceinline__ uint32_t packh2(float lo, float hi) {
    __half2 h = __floats2half2_rn(lo, hi);
    return *reinterpret_cast<uint32_t*>(&h);
}

// ---------------------------------------------------------------- kernel 1: sign(W) -> fp16 (vectorized)
__global__ void sign_kernel(const float* __restrict__ W) {
    int i = blockIdx.x * 256 + threadIdx.x;      // granule = 8 elements
    int n  = i >> 12;                             // 4096 granules per row
    int k8 = i & 4095;
    __half2 h[4];
    if (n < CLASSES) {
        const float4* p = reinterpret_cast<const float4*>(W + ((size_t)n << 15)) + k8 * 2;
        float4 f0 = p[0], f1 = p[1];
        #define SG(v) ((v) > 0.f ? 1.f : ((v) < 0.f ? -1.f : 0.f))
        h[0] = __floats2half2_rn(SG(f0.x), SG(f0.y));
        h[1] = __floats2half2_rn(SG(f0.z), SG(f0.w));
        h[2] = __floats2half2_rn(SG(f1.x), SG(f1.y));
        h[3] = __floats2half2_rn(SG(f1.z), SG(f1.w));
        #undef SG
    } else {
        h[0] = h[1] = h[2] = h[3] = __floats2half2_rn(0.f, 0.f);
    }
    *reinterpret_cast<float4*>(g_signW + (size_t)i * 8) = *reinterpret_cast<float4*>(h);
}

// ---------------------------------------------------------------- kernel 2: split-K fp16 GEMM
__global__ __launch_bounds__(THREADS, 2)
void binmm_kernel(const float* __restrict__ x) {
    extern __shared__ char smraw[];
    uint32_t sb = (smem_u32(smraw) + 1023u) & ~1023u;

    const int tid  = threadIdx.x;
    const int lane = tid & 31;
    const int w    = tid >> 5;
    const int bid  = blockIdx.x;
    const int mtile = bid & 31;
    const int split = bid >> 5;                  // 0..7
    const size_t m0 = (size_t)mtile * 128;
    const int kbase = split * KSPLIT;

    // ---- producer geometry (per thread) ----
    const float* pA[4];
    uint32_t sA[4];
    const __half* pB[4];
    uint32_t sB[4];
    bool bAct[4];
    #pragma unroll
    for (int j = 0; j < 4; j++) {
        int g = tid + THREADS * j;               // A: 1024 granules of 16B smem (8 halves)
        int row = g >> 3, c16 = g & 7;
        pA[j] = x + (m0 + (size_t)row) * IN_DIM + kbase + c16 * 8;
        sA[j] = SWZ((uint32_t)(row * 128 + c16 * 16));
        bAct[j] = g < (NPAD * 8);                // B: 896 granules
        pB[j] = g_signW + (size_t)row * IN_DIM + kbase + c16 * 8;
        sB[j] = sA[j];
    }

    // ---- ldmatrix base addresses ----
    const int lm = lane >> 3, lr = lane & 7;
    const int arow = 16 * w + ((lm & 1) ? 8 : 0) + lr;
    const uint32_t aOff = SWZ((uint32_t)(arow * 128 + (lm >> 1) * 16));
    const int brow = ((lm & 1) ? 8 : 0) + lr;
    const uint32_t bOff = SWZ((uint32_t)(brow * 128 + (lm >> 1) * 16));

    float acc[14][4];
    #pragma unroll
    for (int t = 0; t < 14; t++)
        #pragma unroll
        for (int q = 0; q < 4; q++) acc[t][q] = 0.f;

    float4 fa[4];   // HALF of an A-stage in flight (16 regs) to stay under the occ-2 budget

    #define LOADA2(it, h) do {                                                    \
        _Pragma("unroll")                                                         \
        for (int j = 0; j < 2; j++) {                                             \
            const float* _p = pA[2 * (h) + j] + (size_t)(it) * KSTAGE;            \
            fa[j * 2]     = *reinterpret_cast<const float4*>(_p);                 \
            fa[j * 2 + 1] = *reinterpret_cast<const float4*>(_p + 4);             \
        }                                                                         \
    } while (0)

    #define STSA2(soff, h) do {                                                   \
        _Pragma("unroll")                                                         \
        for (int j = 0; j < 2; j++) {                                             \
            float4 f0 = fa[j * 2], f1 = fa[j * 2 + 1];                            \
            sts128(sb + (soff) + sA[2 * (h) + j],                                 \
                   packh2(f0.x, f0.y), packh2(f0.z, f0.w),                        \
                   packh2(f1.x, f1.y), packh2(f1.z, f1.w));                       \
        }                                                                         \
    } while (0)

    #define CPB(it, soff) do {                                                    \
        _Pragma("unroll")                                                         \
        for (int j = 0; j < 4; j++)                                               \
            if (bAct[j])                                                          \
                cpasync16(sb + (soff) + ABYTES + sB[j], pB[j] + (size_t)(it) * KSTAGE); \
    } while (0)

    #define COMPUTE_HALF(aA, bA, tlo) do {                                        \
        _Pragma("unroll")                                                         \
        for (int t = (tlo); t < (tlo) + 2; t++) {                                 \
            uint32_t a0, a1, a2, a3;                                              \
            ldsm_x4(a0, a1, a2, a3, (aA) ^ (32u * t));                            \
            _Pragma("unroll")                                                     \
            for (int p = 0; p < 7; p++) {                                         \
                uint32_t b0, b1, b2, b3;                                          \
                ldsm_x4(b0, b1, b2, b3, ((bA) + p * 2048) ^ (32u * t));           \
                mma16816(acc[2 * p],     a0, a1, a2, a3, b0, b2);                 \
                mma16816(acc[2 * p + 1], a0, a1, a2, a3, b1, b3);                 \
            }                                                                     \
        }                                                                         \
    } while (0)

    // ---- prologue: stages 0 and 1 ----
    LOADA2(0, 0); STSA2(0, 0); LOADA2(0, 1); STSA2(0, 1); CPB(0, 0);
    asm volatile("cp.async.commit_group;" ::: "memory");
    LOADA2(1, 0); STSA2(STAGE_BYTES, 0); LOADA2(1, 1); STSA2(STAGE_BYTES, 1);
    CPB(1, STAGE_BYTES);
    asm volatile("cp.async.commit_group;" ::: "memory");

    // ---- mainloop ----
    int s = 0;
    for (int i = 0; i < NITER; i++) {
        asm volatile("cp.async.wait_group 1;" ::: "memory");
        __syncthreads();

        const bool pf = (i + 2) < NITER;
        int s2 = s + 2; if (s2 >= 3) s2 -= 3;
        const uint32_t soff  = (uint32_t)s * STAGE_BYTES;
        const uint32_t soff2 = (uint32_t)s2 * STAGE_BYTES;

        if (pf) {
            LOADA2(i + 2, 0);
            CPB(i + 2, soff2);
        }
        asm volatile("cp.async.commit_group;" ::: "memory");

        const uint32_t aA = sb + soff + aOff;
        const uint32_t bA = sb + soff + ABYTES + bOff;

        COMPUTE_HALF(aA, bA, 0);
        if (pf) { STSA2(soff2, 0); LOADA2(i + 2, 1); }
        COMPUTE_HALF(aA, bA, 2);
        if (pf) STSA2(soff2, 1);

        if (++s == 3) s = 0;
    }

    // ---- epilogue: store split-K partials ----
    const int r0 = 16 * w + (lane >> 2);
    #pragma unroll
    for (int nt = 0; nt < 14; nt++) {
        int n = nt * 8 + (lane & 3) * 2;
        size_t idx = ((size_t)split * BATCH + m0 + r0) * NPAD + n;
        *reinterpret_cast<float2*>(&g_partial[idx]) = make_float2(acc[nt][0], acc[nt][1]);
        *reinterpret_cast<float2*>(&g_partial[idx + 8 * NPAD]) = make_float2(acc[nt][2], acc[nt][3]);
    }
    #undef LOADA2
    #undef STSA2
    #undef CPB
    #undef COMPUTE_HALF
}

// ---------------------------------------------------------------- kernel 3: split-K reduce
__global__ void reduce_kernel(float* __restrict__ out) {
    int idx = blockIdx.x * 256 + threadIdx.x;   // BATCH * CLASSES
    int m = idx / CLASSES;
    int n = idx - m * CLASSES;
    const float scale = 0.0055242717280199026f; // 1/sqrt(32768)
    float a = 0.f;
    #pragma unroll
    for (int s = 0; s < SPLITS; s++)
        a += g_partial[((size_t)s * BATCH + m) * NPAD + n];
    out[idx] = a * scale;
}

// ---------------------------------------------------------------- launch
extern "C" void kernel_launch(void* const* d_in, const int* in_sizes, int n_in,
                              void* d_out, int out_size) {
    const float* x = (const float*)d_in[0];
    const float* W = (const float*)d_in[1];
    float* out = (float*)d_out;

    const int SMEM_DYN = 3 * STAGE_BYTES + 1024;
    cudaFuncSetAttribute(binmm_kernel, cudaFuncAttributeMaxDynamicSharedMemorySize, SMEM_DYN);

    sign_kernel<<<(NPAD * IN_DIM / 8) / 256, 256>>>(W);
    binmm_kernel<<<SPLITS * 32, THREADS, SMEM_DYN>>>(x);
    reduce_kernel<<<(BATCH * CLASSES) / 256, 256>>>(out);
}